// round 1
// baseline (speedup 1.0000x reference)
#include <cuda_runtime.h>

// MinConv2d: 3x3 min-pool, stride 1, pad 1 (zero padding PARTICIPATES in min).
// Input/output: (8, 64, 512, 512) fp32 -> 512 planes of 512x512.
//
// Strategy: separable rolling min. Each thread owns a 4-wide column strip
// (float4) across a 32-row tile. For each input row it computes the
// horizontal 3-min once (register float4), then the vertical 3-min is a
// rolling min over the last three horizontal results. Fully coalesced
// 16B loads/stores; the two edge scalars hit L1.

#define PLANE_H 512
#define PLANE_W 512
#define ROWS_PER_BLOCK 32
#define THREADS 128   // 128 * 4 floats = 512 = full row width

__global__ __launch_bounds__(THREADS)
void minpool3x3_kernel(const float* __restrict__ x, float* __restrict__ out) {
    const int plane = blockIdx.y;
    const float* __restrict__ xp = x + (size_t)plane * PLANE_H * PLANE_W;
    float* __restrict__ op = out + (size_t)plane * PLANE_H * PLANE_W;

    const int base = threadIdx.x * 4;          // column offset of this thread's strip
    const int y0   = blockIdx.x * ROWS_PER_BLOCK;

    float4 h2, h1;  // horizontal mins of the previous two input rows

    #pragma unroll 4
    for (int r = -1; r <= ROWS_PER_BLOCK; ++r) {
        const int yi = y0 + r;
        float4 h;
        if (yi < 0 || yi >= PLANE_H) {
            // Padded row: all zeros -> horizontal min is 0 everywhere.
            h = make_float4(0.0f, 0.0f, 0.0f, 0.0f);
        } else {
            const float* row = xp + (size_t)yi * PLANE_W + base;
            const float4 v = *reinterpret_cast<const float4*>(row);
            const float left  = (base == 0)            ? 0.0f : __ldg(row - 1);
            const float right = (base + 4 == PLANE_W)  ? 0.0f : __ldg(row + 4);
            h.x = fminf(left, fminf(v.x, v.y));
            h.y = fminf(v.x,  fminf(v.y, v.z));
            h.z = fminf(v.y,  fminf(v.z, v.w));
            h.w = fminf(v.z,  fminf(v.w, right));
        }

        if (r >= 1) {
            const int yo = yi - 1;   // output row now fully determined
            float4 o;
            o.x = fminf(h2.x, fminf(h1.x, h.x));
            o.y = fminf(h2.y, fminf(h1.y, h.y));
            o.z = fminf(h2.z, fminf(h1.z, h.z));
            o.w = fminf(h2.w, fminf(h1.w, h.w));
            *reinterpret_cast<float4*>(op + (size_t)yo * PLANE_W + base) = o;
        }
        h2 = h1;
        h1 = h;
    }
}

extern "C" void kernel_launch(void* const* d_in, const int* in_sizes, int n_in,
                              void* d_out, int out_size) {
    const float* x = (const float*)d_in[0];
    float* out = (float*)d_out;

    const int planes = 8 * 64;                       // N * C = 512
    dim3 grid(PLANE_H / ROWS_PER_BLOCK, planes);     // (16, 512)
    dim3 block(THREADS);
    minpool3x3_kernel<<<grid, block>>>(x, out);
}